// round 12
// baseline (speedup 1.0000x reference)
#include <cuda_runtime.h>
#include <cuda_fp16.h>
#include <cstdint>

#define Bsz 512
#define D   2048
#define Hh  16
#define DH  128
#define FF  8192

typedef __half half_t;

// ---------------- scratch (__device__ globals; no allocation allowed) --------
__device__ half_t g_h  [Bsz * D];
__device__ float  g_q  [Bsz * D];
__device__ float  g_k  [Bsz * D];
__device__ float  g_v  [Bsz * D];
__device__ half_t g_o  [Bsz * D];
__device__ float  g_x1 [Bsz * D];
__device__ half_t g_h2 [Bsz * D];
__device__ half_t g_f1 [Bsz * FF];
__device__ float  g_P0 [Bsz * D];
__device__ float  g_P1 [Bsz * D];

// ---------------- PTX helpers (base-target instructions only) ----------------
__device__ __forceinline__ uint32_t smem_u32(const void* p) {
    uint32_t a;
    asm("{ .reg .u64 t; cvta.to.shared.u64 t, %1; cvt.u32.u64 %0, t; }" : "=r"(a) : "l"(p));
    return a;
}
__device__ __forceinline__ void cp16(uint32_t dst, const void* src) {
    asm volatile("cp.async.cg.shared.global [%0], [%1], 16;" :: "r"(dst), "l"(src) : "memory");
}
__device__ __forceinline__ void cp_commit() {
    asm volatile("cp.async.commit_group;" ::: "memory");
}
template <int N> __device__ __forceinline__ void cp_wait() {
    asm volatile("cp.async.wait_group %0;" :: "n"(N) : "memory");
}
__device__ __forceinline__ void ldsm4(uint32_t* r, uint32_t addr) {
    asm volatile("ldmatrix.sync.aligned.m8n8.x4.shared.b16 {%0,%1,%2,%3}, [%4];"
        : "=r"(r[0]), "=r"(r[1]), "=r"(r[2]), "=r"(r[3]) : "r"(addr));
}
__device__ __forceinline__ void ldsm4t(uint32_t* r, uint32_t addr) {
    asm volatile("ldmatrix.sync.aligned.m8n8.x4.trans.shared.b16 {%0,%1,%2,%3}, [%4];"
        : "=r"(r[0]), "=r"(r[1]), "=r"(r[2]), "=r"(r[3]) : "r"(addr));
}
__device__ __forceinline__ void mma16816(float* d, const uint32_t* a, const uint32_t* b) {
    asm volatile(
        "mma.sync.aligned.m16n8k16.row.col.f32.f16.f16.f32 "
        "{%0,%1,%2,%3}, {%4,%5,%6,%7}, {%8,%9}, {%0,%1,%2,%3};"
        : "+f"(d[0]), "+f"(d[1]), "+f"(d[2]), "+f"(d[3])
        : "r"(a[0]), "r"(a[1]), "r"(a[2]), "r"(a[3]), "r"(b[0]), "r"(b[1]));
}

// ---------------- LayerNorm: one block per row, fp16 out ---------------------
__global__ void ln_kernel(const float* __restrict__ x, const float* __restrict__ g,
                          const float* __restrict__ b, half_t* __restrict__ o) {
    __shared__ float red[8];
    const int row = blockIdx.x;
    const int tid = threadIdx.x;
    const float* xr = x + (size_t)row * D;

    float vals[8];
    float s = 0.f;
#pragma unroll
    for (int i = 0; i < 8; i++) { vals[i] = xr[tid + i * 256]; s += vals[i]; }
#pragma unroll
    for (int off = 16; off; off >>= 1) s += __shfl_xor_sync(0xffffffffu, s, off);
    if ((tid & 31) == 0) red[tid >> 5] = s;
    __syncthreads();
    s = 0.f;
#pragma unroll
    for (int i = 0; i < 8; i++) s += red[i];
    const float m = s * (1.f / D);
    __syncthreads();

    float s2 = 0.f;
#pragma unroll
    for (int i = 0; i < 8; i++) { float d = vals[i] - m; s2 += d * d; }
#pragma unroll
    for (int off = 16; off; off >>= 1) s2 += __shfl_xor_sync(0xffffffffu, s2, off);
    if ((tid & 31) == 0) red[tid >> 5] = s2;
    __syncthreads();
    s2 = 0.f;
#pragma unroll
    for (int i = 0; i < 8; i++) s2 += red[i];
    const float rstd = rsqrtf(s2 * (1.f / D) + 1e-5f);

#pragma unroll
    for (int i = 0; i < 8; i++) {
        int c = tid + i * 256;
        o[(size_t)row * D + c] = __float2half_rn((vals[i] - m) * rstd * g[c] + b[c]);
    }
}

// ---------------- attention: ONE WARP per (sample, head) ---------------------
#define PDEG 16
__global__ __launch_bounds__(32) void attn_kernel(
    const float* __restrict__ q, const float* __restrict__ k,
    const float* __restrict__ v, half_t* __restrict__ o) {
    const int lane = threadIdx.x;
    const int base = (blockIdx.x >> 4) * D + (blockIdx.x & 15) * DH;

    float kj[4], vj[4], kp[4];
#pragma unroll
    for (int i = 0; i < 4; i++) {
        kj[i] = k[base + lane + 32 * i];
        vj[i] = v[base + lane + 32 * i];
        kp[i] = 1.f;
    }

    float Mv[PDEG + 1], Ms[PDEG + 1];
#pragma unroll
    for (int p = 0; p <= PDEG; p++) {
        float s1 = kp[0] * vj[0] + kp[1] * vj[1] + kp[2] * vj[2] + kp[3] * vj[3];
        float s2 = kp[0] + kp[1] + kp[2] + kp[3];
#pragma unroll
        for (int off = 16; off; off >>= 1) {
            s1 += __shfl_xor_sync(0xffffffffu, s1, off);
            s2 += __shfl_xor_sync(0xffffffffu, s2, off);
        }
        Mv[p] = s1;
        Ms[p] = s2;
#pragma unroll
        for (int i = 0; i < 4; i++) kp[i] *= kj[i];
    }

#pragma unroll
    for (int i = 0; i < 4; i++) {
        const float a = q[base + lane + 32 * i] * 0.08838834764831845f;
        float num = Mv[PDEG];
        float den = Ms[PDEG];
#pragma unroll
        for (int p = PDEG - 1; p >= 0; p--) {
            const float c = a * (1.0f / (float)(p + 1));
            num = Mv[p] + c * num;
            den = Ms[p] + c * den;
        }
        o[base + lane + 32 * i] = __float2half_rn(num / den);
    }
}

// ---------------- fp16 mma.sync GEMM, NT=128, depth-2 B prefetch -------------
// C[M,N] = A[M,K](fp16 K-major) @ B[K,N](fp32 GMEM, converted on the fly).
// A: 4-stage cp.async ring, lookahead 2.
// B: fp32 LDG **two** tiles ahead into double-buffered regs -> fp16 STS into
//    2-slot smem buffer (latency slack ~2 iters >= DRAM latency).
// Single __syncthreads per iteration (validated R7).
// mode 0: QKV fused (bias, out by col>>11).  mode 2: relu(+bias) -> fp16.
// mode 3: raw fp32 partial into P[blockIdx.z].
#define NSTAGE 4
#define SA_B   80
#define ATILE  (128 * SA_B)
#define NTT    128
#define SB_B   (NTT * 2 + 16)           // 272
#define BTILE  (32 * SB_B)              // 8704
#define GSMEM  (NSTAGE * ATILE + 2 * BTILE)   // 58368

__global__ __launch_bounds__(256) void gemm_kernel(
    const half_t* __restrict__ A, int ldA,
    const float* __restrict__ B0, const float* __restrict__ B1, const float* __restrict__ B2,
    int ldB, int headed, int kt_cnt,
    const float* __restrict__ bi0, const float* __restrict__ bi1, const float* __restrict__ bi2,
    float* __restrict__ o0, float* __restrict__ o1,
    half_t* __restrict__ oh, int Nout, int mode)
{
    extern __shared__ char smem[];
    const uint32_t sbase = smem_u32(smem);
    const int tid  = threadIdx.x;
    const int lane = tid & 31, wid = tid >> 5;
    const int wm = wid & 1, wn = wid >> 1;     // warp grid 2 (M) x 4 (N)

    const int row0 = blockIdx.y * 128;
    const int col0 = blockIdx.x * NTT;
    const int kt_off = blockIdx.z * kt_cnt;
    const int nt = kt_cnt;

    // headed-mode: one 128-col tile == one head
    const float* Whead = nullptr;
    if (headed) {
        const int mat = col0 >> 11;
        const float* W = (mat == 0) ? B0 : (mat == 1) ? B1 : B2;
        Whead = W + (size_t)((col0 & 2047) >> 7) * D * DH;
    }

    const uint32_t a_off = (uint32_t)((wm * 64 + (lane & 7) + ((lane >> 3) & 1) * 8) * SA_B
                                      + ((lane >> 4) & 1) * 16);
    const uint32_t b_off = (uint32_t)(((lane & 7) + ((lane >> 3) & 1) * 8) * SB_B
                                      + wn * (NTT / 2) + ((lane >> 4) & 1) * 16);

    // B prefetch: 32x128 fp32 tile, 2 chunks of 8 cols per thread, x2 buffers
    const int br0 = tid >> 4, bc8 = tid & 15;          // rows 0..15 / col chunk
    const int br1 = br0 + 16;                          // rows 16..31
    float4 breg[2][4];

    auto ldg_b = [&](int t, int buf) {
        const int kk = (kt_off + t) * 32;
        const float *p0, *p1;
        if (headed) {
            p0 = Whead + (size_t)(kk + br0) * DH + bc8 * 8;
            p1 = Whead + (size_t)(kk + br1) * DH + bc8 * 8;
        } else {
            p0 = B0 + (size_t)(kk + br0) * ldB + col0 + bc8 * 8;
            p1 = B0 + (size_t)(kk + br1) * ldB + col0 + bc8 * 8;
        }
        breg[buf][0] = *(const float4*)p0;
        breg[buf][1] = *(const float4*)(p0 + 4);
        breg[buf][2] = *(const float4*)p1;
        breg[buf][3] = *(const float4*)(p1 + 4);
    };
    auto sts_b = [&](int slot, int buf) {
        char* sB = smem + NSTAGE * ATILE + slot * BTILE;
        uint4 w0, w1;
        ((__half2*)&w0)[0] = __floats2half2_rn(breg[buf][0].x, breg[buf][0].y);
        ((__half2*)&w0)[1] = __floats2half2_rn(breg[buf][0].z, breg[buf][0].w);
        ((__half2*)&w0)[2] = __floats2half2_rn(breg[buf][1].x, breg[buf][1].y);
        ((__half2*)&w0)[3] = __floats2half2_rn(breg[buf][1].z, breg[buf][1].w);
        ((__half2*)&w1)[0] = __floats2half2_rn(breg[buf][2].x, breg[buf][2].y);
        ((__half2*)&w1)[1] = __floats2half2_rn(breg[buf][2].z, breg[buf][2].w);
        ((__half2*)&w1)[2] = __floats2half2_rn(breg[buf][3].x, breg[buf][3].y);
        ((__half2*)&w1)[3] = __floats2half2_rn(breg[buf][3].z, breg[buf][3].w);
        *(uint4*)(sB + br0 * SB_B + bc8 * 16) = w0;
        *(uint4*)(sB + br1 * SB_B + bc8 * 16) = w1;
    };
    auto load_a = [&](int t, int slot) {
        const int kk = (kt_off + t) * 32;
        const half_t* Ab = A + (size_t)row0 * ldA + kk;
        const uint32_t sA = sbase + slot * ATILE;
#pragma unroll
        for (int i = 0; i < 2; i++) {
            int id = tid + i * 256;
            int r = id >> 2, c = id & 3;
            cp16(sA + (uint32_t)(r * SA_B + c * 16), Ab + (size_t)r * ldA + c * 8);
        }
        cp_commit();
    };

    float acc[4][4][4];
#pragma unroll
    for (int i = 0; i < 4; i++)
#pragma unroll
        for (int j = 0; j < 4; j++)
#pragma unroll
            for (int p = 0; p < 4; p++) acc[i][j][p] = 0.f;

    // prologue: B tiles 0,1 in regs; A stages 0,1 in flight
    ldg_b(0, 0);
    if (nt > 1) ldg_b(1, 1);
    load_a(0, 0);
    if (nt > 1) load_a(1, 1);

    for (int t = 0; t < nt; t++) {
        sts_b(t & 1, t & 1);                  // flush B tile t into its slot
        if (t + 2 < nt) ldg_b(t + 2, t & 1);  // refill the just-flushed buffer
        if (t + 2 < nt) load_a(t + 2, (t + 2) % NSTAGE);
        {
            int rem = nt - 1 - t;
            if (rem >= 2) cp_wait<2>();
            else if (rem == 1) cp_wait<1>();
            else cp_wait<0>();
        }
        __syncthreads();                      // single barrier per iter

        const uint32_t sA = sbase + (t % NSTAGE) * ATILE;
        const uint32_t sB = sbase + NSTAGE * ATILE + (uint32_t)((t & 1) * BTILE);
#pragma unroll
        for (int ks = 0; ks < 2; ks++) {
            uint32_t bfr[2][4];
#pragma unroll
            for (int np = 0; np < 2; np++)
                ldsm4t(bfr[np], sB + b_off + (uint32_t)(ks * 16 * SB_B + np * 32));
            uint32_t afr[4][4];
#pragma unroll
            for (int mt = 0; mt < 4; mt++)
                ldsm4(afr[mt], sA + a_off + (uint32_t)(mt * 16 * SA_B + ks * 32));
#pragma unroll
            for (int mt = 0; mt < 4; mt++)
#pragma unroll
                for (int nc = 0; nc < 4; nc++)
                    mma16816(acc[mt][nc], afr[mt], &bfr[nc >> 1][(nc & 1) * 2]);
        }
    }

    // ---- epilogue -----------------------------------------------------------
    const int rbase  = row0 + wm * 64 + (lane >> 2);
    const int cgbase = col0 + wn * 32 + (lane & 3) * 2;

    if (mode == 0) {
        const int mat = col0 >> 11;
        float* outp = (mat == 0) ? o0 : (mat == 1) ? o1 : (float*)oh;  // oh reused as o2
        const float* bp = (mat == 0) ? bi0 : (mat == 1) ? bi1 : bi2;
        const int clb = cgbase & 2047;
#pragma unroll
        for (int mt = 0; mt < 4; mt++) {
            int r = rbase + mt * 16;
#pragma unroll
            for (int nc = 0; nc < 4; nc++) {
                int cc = clb + nc * 8;
                *(float2*)(outp + (size_t)r * 2048 + cc) =
                    make_float2(acc[mt][nc][0] + bp[cc], acc[mt][nc][1] + bp[cc + 1]);
                *(float2*)(outp + (size_t)(r + 8) * 2048 + cc) =
                    make_float2(acc[mt][nc][2] + bp[cc], acc[mt][nc][3] + bp[cc + 1]);
            }
        }
    } else if (mode == 2) {
#pragma unroll
        for (int mt = 0; mt < 4; mt++) {
            int r = rbase + mt * 16;
#pragma unroll
            for (int nc = 0; nc < 4; nc++) {
                int cc = cgbase + nc * 8;
                float v0 = fmaxf(acc[mt][nc][0] + bi0[cc], 0.f);
                float v1 = fmaxf(acc[mt][nc][1] + bi0[cc + 1], 0.f);
                float v2 = fmaxf(acc[mt][nc][2] + bi0[cc], 0.f);
                float v3 = fmaxf(acc[mt][nc][3] + bi0[cc + 1], 0.f);
                *(__half2*)(oh + (size_t)r * Nout + cc) = __floats2half2_rn(v0, v1);
                *(__half2*)(oh + (size_t)(r + 8) * Nout + cc) = __floats2half2_rn(v2, v3);
            }
        }
    } else {  // mode 3: raw fp32 partial by z
        float* outp = (blockIdx.z == 0) ? o0 : o1;
#pragma unroll
        for (int mt = 0; mt < 4; mt++) {
            int r = rbase + mt * 16;
#pragma unroll
            for (int nc = 0; nc < 4; nc++) {
                int cc = cgbase + nc * 8;
                *(float2*)(outp + (size_t)r * Nout + cc) =
                    make_float2(acc[mt][nc][0], acc[mt][nc][1]);
                *(float2*)(outp + (size_t)(r + 8) * Nout + cc) =
                    make_float2(acc[mt][nc][2], acc[mt][nc][3]);
            }
        }
    }
}

// ---------------- combine 2 partials + bias + residual, then LN --------------
__global__ void combine_ln_kernel(const float* __restrict__ x,
                                  const float* __restrict__ P0, const float* __restrict__ P1,
                                  const float* __restrict__ bias,
                                  const float* __restrict__ g, const float* __restrict__ b,
                                  float* __restrict__ x1, half_t* __restrict__ oh) {
    __shared__ float red[8];
    const int row = blockIdx.x;
    const int tid = threadIdx.x;
    const size_t rb = (size_t)row * D;

    float vals[8];
    float s = 0.f;
#pragma unroll
    for (int i = 0; i < 8; i++) {
        int c = tid + i * 256;
        float v = x[rb + c] + P0[rb + c] + P1[rb + c] + bias[c];
        x1[rb + c] = v;
        vals[i] = v;
        s += v;
    }
#pragma unroll
    for (int off = 16; off; off >>= 1) s += __shfl_xor_sync(0xffffffffu, s, off);
    if ((tid & 31) == 0) red[tid >> 5] = s;
    __syncthreads();
    s = 0.f;
#pragma unroll
    for (int i = 0; i < 8; i++) s += red[i];
    const float m = s * (1.f / D);
    __syncthreads();

    float s2 = 0.f;
#pragma unroll
    for (int i = 0; i < 8; i++) { float d = vals[i] - m; s2 += d * d; }
#pragma unroll
    for (int off = 16; off; off >>= 1) s2 += __shfl_xor_sync(0xffffffffu, s2, off);
    if ((tid & 31) == 0) red[tid >> 5] = s2;
    __syncthreads();
    s2 = 0.f;
#pragma unroll
    for (int i = 0; i < 8; i++) s2 += red[i];
    const float rstd = rsqrtf(s2 * (1.f / D) + 1e-5f);

#pragma unroll
    for (int i = 0; i < 8; i++) {
        int c = tid + i * 256;
        oh[rb + c] = __float2half_rn((vals[i] - m) * rstd * g[c] + b[c]);
    }
}

// ---------------- final combine: out = x1 + P0 + P1 + b2 ---------------------
__global__ void combine_kernel(const float* __restrict__ x1,
                               const float* __restrict__ P0, const float* __restrict__ P1,
                               const float* __restrict__ b2, float* __restrict__ out) {
    size_t i = (size_t)(blockIdx.x * blockDim.x + threadIdx.x) * 4;
    int col = (int)(i & (D - 1));
    float4 a = *(const float4*)(x1 + i);
    float4 p = *(const float4*)(P0 + i);
    float4 q = *(const float4*)(P1 + i);
    float4 b = *(const float4*)(b2 + col);
    float4 w;
    w.x = a.x + p.x + q.x + b.x;
    w.y = a.y + p.y + q.y + b.y;
    w.z = a.z + p.z + q.z + b.z;
    w.w = a.w + p.w + q.w + b.w;
    *(float4*)(out + i) = w;
}

// ---------------- host orchestration -----------------------------------------
extern "C" void kernel_launch(void* const* d_in, const int* in_sizes, int n_in,
                              void* d_out, int out_size) {
    const float* x   = (const float*)d_in[0];
    const float* Wq  = (const float*)d_in[1];
    const float* bq  = (const float*)d_in[2];
    const float* Wk  = (const float*)d_in[3];
    const float* bk  = (const float*)d_in[4];
    const float* Wv  = (const float*)d_in[5];
    const float* bv  = (const float*)d_in[6];
    const float* Wo  = (const float*)d_in[7];
    const float* bo  = (const float*)d_in[8];
    const float* W1  = (const float*)d_in[9];
    const float* b1  = (const float*)d_in[10];
    const float* W2  = (const float*)d_in[11];
    const float* b2  = (const float*)d_in[12];
    const float* g1  = (const float*)d_in[13];
    const float* be1 = (const float*)d_in[14];
    const float* g2  = (const float*)d_in[15];
    const float* be2 = (const float*)d_in[16];
    float* out = (float*)d_out;

    half_t *ph, *po, *ph2, *pf1;
    float *pq, *pk, *pv, *px1, *pP0, *pP1;
    cudaGetSymbolAddress((void**)&ph,  g_h);
    cudaGetSymbolAddress((void**)&pq,  g_q);
    cudaGetSymbolAddress((void**)&pk,  g_k);
    cudaGetSymbolAddress((void**)&pv,  g_v);
    cudaGetSymbolAddress((void**)&po,  g_o);
    cudaGetSymbolAddress((void**)&px1, g_x1);
    cudaGetSymbolAddress((void**)&ph2, g_h2);
    cudaGetSymbolAddress((void**)&pf1, g_f1);
    cudaGetSymbolAddress((void**)&pP0, g_P0);
    cudaGetSymbolAddress((void**)&pP1, g_P1);

    static bool attr_done = false;
    if (!attr_done) {
        cudaFuncSetAttribute(gemm_kernel, cudaFuncAttributeMaxDynamicSharedMemorySize, GSMEM);
        attr_done = true;
    }

    // ---- h = LN(x) ----
    ln_kernel<<<Bsz, 256>>>(x, g1, be1, ph);

    // ---- q|k|v = h @ [Wq|Wk|Wv] + b (headed): 192 CTAs, kt=64 ----
    gemm_kernel<<<dim3(3 * D / NTT, Bsz / 128, 1), 256, GSMEM>>>(
        ph, D, Wq, Wk, Wv, 0, 1, D / 32,
        bq, bk, bv, pq, pk, (half_t*)pv, 2048, 0);

    // ---- attention (warp-only) ----
    attn_kernel<<<Bsz * Hh, 32>>>(pq, pk, pv, po);

    // ---- P_z = o @ Wo (K-split x2): 128 CTAs, kt=32 ----
    gemm_kernel<<<dim3(D / NTT, Bsz / 128, 2), 256, GSMEM>>>(
        po, D, Wo, nullptr, nullptr, D, 0, (D / 2) / 32,
        nullptr, nullptr, nullptr, pP0, pP1, nullptr, D, 3);

    // ---- x1 = x + P0 + P1 + bo; h2 = LN(x1) (fused) ----
    combine_ln_kernel<<<Bsz, 256>>>(x, pP0, pP1, bo, g2, be2, px1, ph2);

    // ---- f1 = relu(h2 @ W1 + b1) -> fp16: 256 CTAs, kt=64 ----
    gemm_kernel<<<dim3(FF / NTT, Bsz / 128, 1), 256, GSMEM>>>(
        ph2, D, W1, nullptr, nullptr, FF, 0, D / 32,
        b1, nullptr, nullptr, nullptr, nullptr, pf1, FF, 2);

    // ---- P_z = f1 @ W2 (K-split x2): 128 CTAs, kt=128 ----
    gemm_kernel<<<dim3(D / NTT, Bsz / 128, 2), 256, GSMEM>>>(
        pf1, FF, W2, nullptr, nullptr, D, 0, (FF / 2) / 32,
        nullptr, nullptr, nullptr, pP0, pP1, nullptr, D, 3);

    // ---- out = x1 + P0 + P1 + b2 ----
    combine_kernel<<<(Bsz * D / 4) / 512, 512>>>(px1, pP0, pP1, b2, out);
}

// round 13
// speedup vs baseline: 1.6820x; 1.6820x over previous
#include <cuda_runtime.h>
#include <cuda_fp16.h>
#include <cstdint>

#define Bsz 512
#define D   2048
#define Hh  16
#define DH  128
#define FF  8192

typedef __half half_t;

// ---------------- scratch (__device__ globals; no allocation allowed) --------
__device__ half_t g_h  [Bsz * D];
__device__ float  g_q  [Bsz * D];
__device__ float  g_k  [Bsz * D];
__device__ float  g_v  [Bsz * D];
__device__ half_t g_o  [Bsz * D];
__device__ float  g_x1 [Bsz * D];
__device__ half_t g_h2 [Bsz * D];
__device__ half_t g_f1 [Bsz * FF];
__device__ float  g_P0 [Bsz * D];
__device__ float  g_P1 [Bsz * D];

// ---------------- PTX helpers (base-target instructions only) ----------------
__device__ __forceinline__ uint32_t smem_u32(const void* p) {
    uint32_t a;
    asm("{ .reg .u64 t; cvta.to.shared.u64 t, %1; cvt.u32.u64 %0, t; }" : "=r"(a) : "l"(p));
    return a;
}
__device__ __forceinline__ void cp16(uint32_t dst, const void* src) {
    asm volatile("cp.async.cg.shared.global [%0], [%1], 16;" :: "r"(dst), "l"(src) : "memory");
}
__device__ __forceinline__ void cp_commit() {
    asm volatile("cp.async.commit_group;" ::: "memory");
}
template <int N> __device__ __forceinline__ void cp_wait() {
    asm volatile("cp.async.wait_group %0;" :: "n"(N) : "memory");
}
__device__ __forceinline__ void ldsm4(uint32_t* r, uint32_t addr) {
    asm volatile("ldmatrix.sync.aligned.m8n8.x4.shared.b16 {%0,%1,%2,%3}, [%4];"
        : "=r"(r[0]), "=r"(r[1]), "=r"(r[2]), "=r"(r[3]) : "r"(addr));
}
__device__ __forceinline__ void ldsm4t(uint32_t* r, uint32_t addr) {
    asm volatile("ldmatrix.sync.aligned.m8n8.x4.trans.shared.b16 {%0,%1,%2,%3}, [%4];"
        : "=r"(r[0]), "=r"(r[1]), "=r"(r[2]), "=r"(r[3]) : "r"(addr));
}
__device__ __forceinline__ void mma16816(float* d, const uint32_t* a, const uint32_t* b) {
    asm volatile(
        "mma.sync.aligned.m16n8k16.row.col.f32.f16.f16.f32 "
        "{%0,%1,%2,%3}, {%4,%5,%6,%7}, {%8,%9}, {%0,%1,%2,%3};"
        : "+f"(d[0]), "+f"(d[1]), "+f"(d[2]), "+f"(d[3])
        : "r"(a[0]), "r"(a[1]), "r"(a[2]), "r"(a[3]), "r"(b[0]), "r"(b[1]));
}

// ---------------- LayerNorm: one block per row, fp16 out ---------------------
__global__ void ln_kernel(const float* __restrict__ x, const float* __restrict__ g,
                          const float* __restrict__ b, half_t* __restrict__ o) {
    __shared__ float red[8];
    const int row = blockIdx.x;
    const int tid = threadIdx.x;
    const float* xr = x + (size_t)row * D;

    float vals[8];
    float s = 0.f;
#pragma unroll
    for (int i = 0; i < 8; i++) { vals[i] = xr[tid + i * 256]; s += vals[i]; }
#pragma unroll
    for (int off = 16; off; off >>= 1) s += __shfl_xor_sync(0xffffffffu, s, off);
    if ((tid & 31) == 0) red[tid >> 5] = s;
    __syncthreads();
    s = 0.f;
#pragma unroll
    for (int i = 0; i < 8; i++) s += red[i];
    const float m = s * (1.f / D);
    __syncthreads();

    float s2 = 0.f;
#pragma unroll
    for (int i = 0; i < 8; i++) { float d = vals[i] - m; s2 += d * d; }
#pragma unroll
    for (int off = 16; off; off >>= 1) s2 += __shfl_xor_sync(0xffffffffu, s2, off);
    if ((tid & 31) == 0) red[tid >> 5] = s2;
    __syncthreads();
    s2 = 0.f;
#pragma unroll
    for (int i = 0; i < 8; i++) s2 += red[i];
    const float rstd = rsqrtf(s2 * (1.f / D) + 1e-5f);

#pragma unroll
    for (int i = 0; i < 8; i++) {
        int c = tid + i * 256;
        o[(size_t)row * D + c] = __float2half_rn((vals[i] - m) * rstd * g[c] + b[c]);
    }
}

// ---------------- attention: ONE WARP per (sample, head) ---------------------
#define PDEG 16
__global__ __launch_bounds__(32) void attn_kernel(
    const float* __restrict__ q, const float* __restrict__ k,
    const float* __restrict__ v, half_t* __restrict__ o) {
    const int lane = threadIdx.x;
    const int base = (blockIdx.x >> 4) * D + (blockIdx.x & 15) * DH;

    float kj[4], vj[4], kp[4];
#pragma unroll
    for (int i = 0; i < 4; i++) {
        kj[i] = k[base + lane + 32 * i];
        vj[i] = v[base + lane + 32 * i];
        kp[i] = 1.f;
    }

    float Mv[PDEG + 1], Ms[PDEG + 1];
#pragma unroll
    for (int p = 0; p <= PDEG; p++) {
        float s1 = kp[0] * vj[0] + kp[1] * vj[1] + kp[2] * vj[2] + kp[3] * vj[3];
        float s2 = kp[0] + kp[1] + kp[2] + kp[3];
#pragma unroll
        for (int off = 16; off; off >>= 1) {
            s1 += __shfl_xor_sync(0xffffffffu, s1, off);
            s2 += __shfl_xor_sync(0xffffffffu, s2, off);
        }
        Mv[p] = s1;
        Ms[p] = s2;
#pragma unroll
        for (int i = 0; i < 4; i++) kp[i] *= kj[i];
    }

#pragma unroll
    for (int i = 0; i < 4; i++) {
        const float a = q[base + lane + 32 * i] * 0.08838834764831845f;
        float num = Mv[PDEG];
        float den = Ms[PDEG];
#pragma unroll
        for (int p = PDEG - 1; p >= 0; p--) {
            const float c = a * (1.0f / (float)(p + 1));
            num = Mv[p] + c * num;
            den = Ms[p] + c * den;
        }
        o[base + lane + 32 * i] = __float2half_rn(num / den);
    }
}

// ---------------- fp16 mma.sync GEMM, NT=128, depth-2 B prefetch -------------
// Mainloop manually unrolled x2 so BOTH B register buffers have compile-time
// indices (R12's runtime-indexed breg spilled to local memory -> 2x slowdown).
// even sub-iter: slot0/breg0; odd sub-iter: slot1/breg1.  kt_cnt must be even
// (all call sites: 64, 32, 64, 128).
// A: 4-stage cp.async ring, lookahead 2.  One __syncthreads per sub-iter.
// mode 0: QKV fused (bias, out by col>>11).  mode 2: relu(+bias) -> fp16.
// mode 3: raw fp32 partial into P[blockIdx.z].
#define NSTAGE 4
#define SA_B   80
#define ATILE  (128 * SA_B)
#define NTT    128
#define SB_B   (NTT * 2 + 16)           // 272
#define BTILE  (32 * SB_B)              // 8704
#define GSMEM  (NSTAGE * ATILE + 2 * BTILE)   // 58368

__global__ __launch_bounds__(256) void gemm_kernel(
    const half_t* __restrict__ A, int ldA,
    const float* __restrict__ B0, const float* __restrict__ B1, const float* __restrict__ B2,
    int ldB, int headed, int kt_cnt,
    const float* __restrict__ bi0, const float* __restrict__ bi1, const float* __restrict__ bi2,
    float* __restrict__ o0, float* __restrict__ o1,
    half_t* __restrict__ oh, int Nout, int mode)
{
    extern __shared__ char smem[];
    const uint32_t sbase = smem_u32(smem);
    const int tid  = threadIdx.x;
    const int lane = tid & 31, wid = tid >> 5;
    const int wm = wid & 1, wn = wid >> 1;     // warp grid 2 (M) x 4 (N)

    const int row0 = blockIdx.y * 128;
    const int col0 = blockIdx.x * NTT;
    const int kt_off = blockIdx.z * kt_cnt;
    const int nt = kt_cnt;

    // headed-mode: one 128-col tile == one head
    const float* Whead = nullptr;
    if (headed) {
        const int mat = col0 >> 11;
        const float* W = (mat == 0) ? B0 : (mat == 1) ? B1 : B2;
        Whead = W + (size_t)((col0 & 2047) >> 7) * D * DH;
    }

    const uint32_t a_off = (uint32_t)((wm * 64 + (lane & 7) + ((lane >> 3) & 1) * 8) * SA_B
                                      + ((lane >> 4) & 1) * 16);
    const uint32_t b_off = (uint32_t)(((lane & 7) + ((lane >> 3) & 1) * 8) * SB_B
                                      + wn * (NTT / 2) + ((lane >> 4) & 1) * 16);

    // B prefetch: 32x128 fp32 tile, 2 row-chunks of 8 cols per thread
    const int br0 = tid >> 4, bc8 = tid & 15;
    const int br1 = br0 + 16;
    float4 breg0[4], breg1[4];                 // two named buffers, const idx

    auto ldg_b = [&](int t, float4 (&br)[4]) {
        const int kk = (kt_off + t) * 32;
        const float *p0, *p1;
        if (headed) {
            p0 = Whead + (size_t)(kk + br0) * DH + bc8 * 8;
            p1 = Whead + (size_t)(kk + br1) * DH + bc8 * 8;
        } else {
            p0 = B0 + (size_t)(kk + br0) * ldB + col0 + bc8 * 8;
            p1 = B0 + (size_t)(kk + br1) * ldB + col0 + bc8 * 8;
        }
        br[0] = *(const float4*)p0;
        br[1] = *(const float4*)(p0 + 4);
        br[2] = *(const float4*)p1;
        br[3] = *(const float4*)(p1 + 4);
    };
    auto sts_b = [&](int slot, const float4 (&br)[4]) {
        char* sB = smem + NSTAGE * ATILE + slot * BTILE;
        uint4 w0, w1;
        ((__half2*)&w0)[0] = __floats2half2_rn(br[0].x, br[0].y);
        ((__half2*)&w0)[1] = __floats2half2_rn(br[0].z, br[0].w);
        ((__half2*)&w0)[2] = __floats2half2_rn(br[1].x, br[1].y);
        ((__half2*)&w0)[3] = __floats2half2_rn(br[1].z, br[1].w);
        ((__half2*)&w1)[0] = __floats2half2_rn(br[2].x, br[2].y);
        ((__half2*)&w1)[1] = __floats2half2_rn(br[2].z, br[2].w);
        ((__half2*)&w1)[2] = __floats2half2_rn(br[3].x, br[3].y);
        ((__half2*)&w1)[3] = __floats2half2_rn(br[3].z, br[3].w);
        *(uint4*)(sB + br0 * SB_B + bc8 * 16) = w0;
        *(uint4*)(sB + br1 * SB_B + bc8 * 16) = w1;
    };
    auto load_a = [&](int t, int slot) {
        const int kk = (kt_off + t) * 32;
        const half_t* Ab = A + (size_t)row0 * ldA + kk;
        const uint32_t sA = sbase + slot * ATILE;
#pragma unroll
        for (int i = 0; i < 2; i++) {
            int id = tid + i * 256;
            int r = id >> 2, c = id & 3;
            cp16(sA + (uint32_t)(r * SA_B + c * 16), Ab + (size_t)r * ldA + c * 8);
        }
        cp_commit();
    };

    float acc[4][4][4];
#pragma unroll
    for (int i = 0; i < 4; i++)
#pragma unroll
        for (int j = 0; j < 4; j++)
#pragma unroll
            for (int p = 0; p < 4; p++) acc[i][j][p] = 0.f;

    auto pipe_wait = [&](int u) {               // u = global sub-iter index
        int rem = nt - 1 - u;
        if (rem >= 2) cp_wait<2>();
        else if (rem == 1) cp_wait<1>();
        else cp_wait<0>();
    };
    auto compute = [&](int u) {                 // consume slot u&1, stage u%4
        const uint32_t sA = sbase + (u % NSTAGE) * ATILE;
        const uint32_t sB = sbase + NSTAGE * ATILE + (uint32_t)((u & 1) * BTILE);
#pragma unroll
        for (int ks = 0; ks < 2; ks++) {
            uint32_t bfr[2][4];
#pragma unroll
            for (int np = 0; np < 2; np++)
                ldsm4t(bfr[np], sB + b_off + (uint32_t)(ks * 16 * SB_B + np * 32));
            uint32_t afr[4][4];
#pragma unroll
            for (int mt = 0; mt < 4; mt++)
                ldsm4(afr[mt], sA + a_off + (uint32_t)(mt * 16 * SA_B + ks * 32));
#pragma unroll
            for (int mt = 0; mt < 4; mt++)
#pragma unroll
                for (int nc = 0; nc < 4; nc++)
                    mma16816(acc[mt][nc], afr[mt], &bfr[nc >> 1][(nc & 1) * 2]);
        }
    };

    // prologue: B tiles 0,1 in the two reg buffers; A stages 0,1 in flight
    ldg_b(0, breg0);
    if (nt > 1) ldg_b(1, breg1);
    load_a(0, 0);
    if (nt > 1) load_a(1, 1);

    for (int t = 0; t < nt; t += 2) {
        // ---- even sub-iter: tile t, slot 0, breg0 ----
        sts_b(0, breg0);
        if (t + 2 < nt) ldg_b(t + 2, breg0);
        if (t + 2 < nt) load_a(t + 2, (t + 2) % NSTAGE);
        pipe_wait(t);
        __syncthreads();
        compute(t);

        // ---- odd sub-iter: tile t+1, slot 1, breg1 ----
        sts_b(1, breg1);
        if (t + 3 < nt) ldg_b(t + 3, breg1);
        if (t + 3 < nt) load_a(t + 3, (t + 3) % NSTAGE);
        pipe_wait(t + 1);
        __syncthreads();
        compute(t + 1);
    }

    // ---- epilogue -----------------------------------------------------------
    const int rbase  = row0 + wm * 64 + (lane >> 2);
    const int cgbase = col0 + wn * 32 + (lane & 3) * 2;

    if (mode == 0) {
        const int mat = col0 >> 11;
        float* outp = (mat == 0) ? o0 : (mat == 1) ? o1 : (float*)oh;  // oh doubles as o2
        const float* bp = (mat == 0) ? bi0 : (mat == 1) ? bi1 : bi2;
        const int clb = cgbase & 2047;
#pragma unroll
        for (int mt = 0; mt < 4; mt++) {
            int r = rbase + mt * 16;
#pragma unroll
            for (int nc = 0; nc < 4; nc++) {
                int cc = clb + nc * 8;
                *(float2*)(outp + (size_t)r * 2048 + cc) =
                    make_float2(acc[mt][nc][0] + bp[cc], acc[mt][nc][1] + bp[cc + 1]);
                *(float2*)(outp + (size_t)(r + 8) * 2048 + cc) =
                    make_float2(acc[mt][nc][2] + bp[cc], acc[mt][nc][3] + bp[cc + 1]);
            }
        }
    } else if (mode == 2) {
#pragma unroll
        for (int mt = 0; mt < 4; mt++) {
            int r = rbase + mt * 16;
#pragma unroll
            for (int nc = 0; nc < 4; nc++) {
                int cc = cgbase + nc * 8;
                float v0 = fmaxf(acc[mt][nc][0] + bi0[cc], 0.f);
                float v1 = fmaxf(acc[mt][nc][1] + bi0[cc + 1], 0.f);
                float v2 = fmaxf(acc[mt][nc][2] + bi0[cc], 0.f);
                float v3 = fmaxf(acc[mt][nc][3] + bi0[cc + 1], 0.f);
                *(__half2*)(oh + (size_t)r * Nout + cc) = __floats2half2_rn(v0, v1);
                *(__half2*)(oh + (size_t)(r + 8) * Nout + cc) = __floats2half2_rn(v2, v3);
            }
        }
    } else {  // mode 3: raw fp32 partial by z
        float* outp = (blockIdx.z == 0) ? o0 : o1;
#pragma unroll
        for (int mt = 0; mt < 4; mt++) {
            int r = rbase + mt * 16;
#pragma unroll
            for (int nc = 0; nc < 4; nc++) {
                int cc = cgbase + nc * 8;
                *(float2*)(outp + (size_t)r * Nout + cc) =
                    make_float2(acc[mt][nc][0], acc[mt][nc][1]);
                *(float2*)(outp + (size_t)(r + 8) * Nout + cc) =
                    make_float2(acc[mt][nc][2], acc[mt][nc][3]);
            }
        }
    }
}

// ---------------- combine 2 partials + bias + residual, then LN --------------
__global__ void combine_ln_kernel(const float* __restrict__ x,
                                  const float* __restrict__ P0, const float* __restrict__ P1,
                                  const float* __restrict__ bias,
                                  const float* __restrict__ g, const float* __restrict__ b,
                                  float* __restrict__ x1, half_t* __restrict__ oh) {
    __shared__ float red[8];
    const int row = blockIdx.x;
    const int tid = threadIdx.x;
    const size_t rb = (size_t)row * D;

    float vals[8];
    float s = 0.f;
#pragma unroll
    for (int i = 0; i < 8; i++) {
        int c = tid + i * 256;
        float v = x[rb + c] + P0[rb + c] + P1[rb + c] + bias[c];
        x1[rb + c] = v;
        vals[i] = v;
        s += v;
    }
#pragma unroll
    for (int off = 16; off; off >>= 1) s += __shfl_xor_sync(0xffffffffu, s, off);
    if ((tid & 31) == 0) red[tid >> 5] = s;
    __syncthreads();
    s = 0.f;
#pragma unroll
    for (int i = 0; i < 8; i++) s += red[i];
    const float m = s * (1.f / D);
    __syncthreads();

    float s2 = 0.f;
#pragma unroll
    for (int i = 0; i < 8; i++) { float d = vals[i] - m; s2 += d * d; }
#pragma unroll
    for (int off = 16; off; off >>= 1) s2 += __shfl_xor_sync(0xffffffffu, s2, off);
    if ((tid & 31) == 0) red[tid >> 5] = s2;
    __syncthreads();
    s2 = 0.f;
#pragma unroll
    for (int i = 0; i < 8; i++) s2 += red[i];
    const float rstd = rsqrtf(s2 * (1.f / D) + 1e-5f);

#pragma unroll
    for (int i = 0; i < 8; i++) {
        int c = tid + i * 256;
        oh[rb + c] = __float2half_rn((vals[i] - m) * rstd * g[c] + b[c]);
    }
}

// ---------------- final combine: out = x1 + P0 + P1 + b2 ---------------------
__global__ void combine_kernel(const float* __restrict__ x1,
                               const float* __restrict__ P0, const float* __restrict__ P1,
                               const float* __restrict__ b2, float* __restrict__ out) {
    size_t i = (size_t)(blockIdx.x * blockDim.x + threadIdx.x) * 4;
    int col = (int)(i & (D - 1));
    float4 a = *(const float4*)(x1 + i);
    float4 p = *(const float4*)(P0 + i);
    float4 q = *(const float4*)(P1 + i);
    float4 b = *(const float4*)(b2 + col);
    float4 w;
    w.x = a.x + p.x + q.x + b.x;
    w.y = a.y + p.y + q.y + b.y;
    w.z = a.z + p.z + q.z + b.z;
    w.w = a.w + p.w + q.w + b.w;
    *(float4*)(out + i) = w;
}

// ---------------- host orchestration -----------------------------------------
extern "C" void kernel_launch(void* const* d_in, const int* in_sizes, int n_in,
                              void* d_out, int out_size) {
    const float* x   = (const float*)d_in[0];
    const float* Wq  = (const float*)d_in[1];
    const float* bq  = (const float*)d_in[2];
    const float* Wk  = (const float*)d_in[3];
    const float* bk  = (const float*)d_in[4];
    const float* Wv  = (const float*)d_in[5];
    const float* bv  = (const float*)d_in[6];
    const float* Wo  = (const float*)d_in[7];
    const float* bo  = (const float*)d_in[8];
    const float* W1  = (const float*)d_in[9];
    const float* b1  = (const float*)d_in[10];
    const float* W2  = (const float*)d_in[11];
    const float* b2  = (const float*)d_in[12];
    const float* g1  = (const float*)d_in[13];
    const float* be1 = (const float*)d_in[14];
    const float* g2  = (const float*)d_in[15];
    const float* be2 = (const float*)d_in[16];
    float* out = (float*)d_out;

    half_t *ph, *po, *ph2, *pf1;
    float *pq, *pk, *pv, *px1, *pP0, *pP1;
    cudaGetSymbolAddress((void**)&ph,  g_h);
    cudaGetSymbolAddress((void**)&pq,  g_q);
    cudaGetSymbolAddress((void**)&pk,  g_k);
    cudaGetSymbolAddress((void**)&pv,  g_v);
    cudaGetSymbolAddress((void**)&po,  g_o);
    cudaGetSymbolAddress((void**)&px1, g_x1);
    cudaGetSymbolAddress((void**)&ph2, g_h2);
    cudaGetSymbolAddress((void**)&pf1, g_f1);
    cudaGetSymbolAddress((void**)&pP0, g_P0);
    cudaGetSymbolAddress((void**)&pP1, g_P1);

    static bool attr_done = false;
    if (!attr_done) {
        cudaFuncSetAttribute(gemm_kernel, cudaFuncAttributeMaxDynamicSharedMemorySize, GSMEM);
        attr_done = true;
    }

    // ---- h = LN(x) ----
    ln_kernel<<<Bsz, 256>>>(x, g1, be1, ph);

    // ---- q|k|v = h @ [Wq|Wk|Wv] + b (headed): 192 CTAs, kt=64 ----
    gemm_kernel<<<dim3(3 * D / NTT, Bsz / 128, 1), 256, GSMEM>>>(
        ph, D, Wq, Wk, Wv, 0, 1, D / 32,
        bq, bk, bv, pq, pk, (half_t*)pv, 2048, 0);

    // ---- attention (warp-only) ----
    attn_kernel<<<Bsz * Hh, 32>>>(pq, pk, pv, po);

    // ---- P_z = o @ Wo (K-split x2): 128 CTAs, kt=32 ----
    gemm_kernel<<<dim3(D / NTT, Bsz / 128, 2), 256, GSMEM>>>(
        po, D, Wo, nullptr, nullptr, D, 0, (D / 2) / 32,
        nullptr, nullptr, nullptr, pP0, pP1, nullptr, D, 3);

    // ---- x1 = x + P0 + P1 + bo; h2 = LN(x1) (fused) ----
    combine_ln_kernel<<<Bsz, 256>>>(x, pP0, pP1, bo, g2, be2, px1, ph2);

    // ---- f1 = relu(h2 @ W1 + b1) -> fp16: 256 CTAs, kt=64 ----
    gemm_kernel<<<dim3(FF / NTT, Bsz / 128, 1), 256, GSMEM>>>(
        ph2, D, W1, nullptr, nullptr, FF, 0, D / 32,
        b1, nullptr, nullptr, nullptr, nullptr, pf1, FF, 2);

    // ---- P_z = f1 @ W2 (K-split x2): 128 CTAs, kt=128 ----
    gemm_kernel<<<dim3(D / NTT, Bsz / 128, 2), 256, GSMEM>>>(
        pf1, FF, W2, nullptr, nullptr, D, 0, (FF / 2) / 32,
        nullptr, nullptr, nullptr, pP0, pP1, nullptr, D, 3);

    // ---- out = x1 + P0 + P1 + b2 ----
    combine_kernel<<<(Bsz * D / 4) / 512, 512>>>(px1, pP0, pP1, b2, out);
}

// round 14
// speedup vs baseline: 2.0276x; 1.2055x over previous
#include <cuda_runtime.h>
#include <cuda_fp16.h>
#include <cstdint>

#define Bsz 512
#define D   2048
#define Hh  16
#define DH  128
#define FF  8192

typedef __half half_t;

// ---------------- scratch (__device__ globals; no allocation allowed) --------
__device__ half_t g_h  [Bsz * D];
__device__ float  g_q  [Bsz * D];
__device__ float  g_k  [Bsz * D];
__device__ float  g_v  [Bsz * D];
__device__ half_t g_o  [Bsz * D];
__device__ float  g_x1 [Bsz * D];
__device__ half_t g_h2 [Bsz * D];
__device__ half_t g_f1 [Bsz * FF];
__device__ float  g_P0 [Bsz * D];
__device__ float  g_P1 [Bsz * D];
__device__ float  g_P2 [Bsz * D];
__device__ float  g_P3 [Bsz * D];

// ---------------- PTX helpers (base-target instructions only) ----------------
__device__ __forceinline__ uint32_t smem_u32(const void* p) {
    uint32_t a;
    asm("{ .reg .u64 t; cvta.to.shared.u64 t, %1; cvt.u32.u64 %0, t; }" : "=r"(a) : "l"(p));
    return a;
}
__device__ __forceinline__ void cp16(uint32_t dst, const void* src) {
    asm volatile("cp.async.cg.shared.global [%0], [%1], 16;" :: "r"(dst), "l"(src) : "memory");
}
__device__ __forceinline__ void cp_commit() {
    asm volatile("cp.async.commit_group;" ::: "memory");
}
template <int N> __device__ __forceinline__ void cp_wait() {
    asm volatile("cp.async.wait_group %0;" :: "n"(N) : "memory");
}
__device__ __forceinline__ void ldsm4(uint32_t* r, uint32_t addr) {
    asm volatile("ldmatrix.sync.aligned.m8n8.x4.shared.b16 {%0,%1,%2,%3}, [%4];"
        : "=r"(r[0]), "=r"(r[1]), "=r"(r[2]), "=r"(r[3]) : "r"(addr));
}
__device__ __forceinline__ void ldsm4t(uint32_t* r, uint32_t addr) {
    asm volatile("ldmatrix.sync.aligned.m8n8.x4.trans.shared.b16 {%0,%1,%2,%3}, [%4];"
        : "=r"(r[0]), "=r"(r[1]), "=r"(r[2]), "=r"(r[3]) : "r"(addr));
}
__device__ __forceinline__ void mma16816(float* d, const uint32_t* a, const uint32_t* b) {
    asm volatile(
        "mma.sync.aligned.m16n8k16.row.col.f32.f16.f16.f32 "
        "{%0,%1,%2,%3}, {%4,%5,%6,%7}, {%8,%9}, {%0,%1,%2,%3};"
        : "+f"(d[0]), "+f"(d[1]), "+f"(d[2]), "+f"(d[3])
        : "r"(a[0]), "r"(a[1]), "r"(a[2]), "r"(a[3]), "r"(b[0]), "r"(b[1]));
}

// ---------------- LayerNorm: one block per row, fp16 out ---------------------
__global__ void ln_kernel(const float* __restrict__ x, const float* __restrict__ g,
                          const float* __restrict__ b, half_t* __restrict__ o) {
    __shared__ float red[8];
    const int row = blockIdx.x;
    const int tid = threadIdx.x;
    const float* xr = x + (size_t)row * D;

    float vals[8];
    float s = 0.f;
#pragma unroll
    for (int i = 0; i < 8; i++) { vals[i] = xr[tid + i * 256]; s += vals[i]; }
#pragma unroll
    for (int off = 16; off; off >>= 1) s += __shfl_xor_sync(0xffffffffu, s, off);
    if ((tid & 31) == 0) red[tid >> 5] = s;
    __syncthreads();
    s = 0.f;
#pragma unroll
    for (int i = 0; i < 8; i++) s += red[i];
    const float m = s * (1.f / D);
    __syncthreads();

    float s2 = 0.f;
#pragma unroll
    for (int i = 0; i < 8; i++) { float d = vals[i] - m; s2 += d * d; }
#pragma unroll
    for (int off = 16; off; off >>= 1) s2 += __shfl_xor_sync(0xffffffffu, s2, off);
    if ((tid & 31) == 0) red[tid >> 5] = s2;
    __syncthreads();
    s2 = 0.f;
#pragma unroll
    for (int i = 0; i < 8; i++) s2 += red[i];
    const float rstd = rsqrtf(s2 * (1.f / D) + 1e-5f);

#pragma unroll
    for (int i = 0; i < 8; i++) {
        int c = tid + i * 256;
        o[(size_t)row * D + c] = __float2half_rn((vals[i] - m) * rstd * g[c] + b[c]);
    }
}

// ---------------- attention: ONE WARP per (sample, head) ---------------------
#define PDEG 16
__global__ __launch_bounds__(32) void attn_kernel(
    const float* __restrict__ q, const float* __restrict__ k,
    const float* __restrict__ v, half_t* __restrict__ o) {
    const int lane = threadIdx.x;
    const int base = (blockIdx.x >> 4) * D + (blockIdx.x & 15) * DH;

    float kj[4], vj[4], kp[4];
#pragma unroll
    for (int i = 0; i < 4; i++) {
        kj[i] = k[base + lane + 32 * i];
        vj[i] = v[base + lane + 32 * i];
        kp[i] = 1.f;
    }

    float Mv[PDEG + 1], Ms[PDEG + 1];
#pragma unroll
    for (int p = 0; p <= PDEG; p++) {
        float s1 = kp[0] * vj[0] + kp[1] * vj[1] + kp[2] * vj[2] + kp[3] * vj[3];
        float s2 = kp[0] + kp[1] + kp[2] + kp[3];
#pragma unroll
        for (int off = 16; off; off >>= 1) {
            s1 += __shfl_xor_sync(0xffffffffu, s1, off);
            s2 += __shfl_xor_sync(0xffffffffu, s2, off);
        }
        Mv[p] = s1;
        Ms[p] = s2;
#pragma unroll
        for (int i = 0; i < 4; i++) kp[i] *= kj[i];
    }

#pragma unroll
    for (int i = 0; i < 4; i++) {
        const float a = q[base + lane + 32 * i] * 0.08838834764831845f;
        float num = Mv[PDEG];
        float den = Ms[PDEG];
#pragma unroll
        for (int p = PDEG - 1; p >= 0; p--) {
            const float c = a * (1.0f / (float)(p + 1));
            num = Mv[p] + c * num;
            den = Ms[p] + c * den;
        }
        o[base + lane + 32 * i] = __float2half_rn(num / den);
    }
}

// ---------------- fp16 mma.sync GEMM, templated N-tile -----------------------
// (structure validated R7/R9: single barrier/iter, A 4-ring lookahead-2,
//  B fp32 LDG 1 tile ahead -> fp16 STS 2-slot)
#define NSTAGE 4
#define SA_B   80
#define ATILE  (128 * SA_B)

template <int NTT>
__global__ __launch_bounds__(256) void gemm_kernel(
    const half_t* __restrict__ A, int ldA,
    const float* __restrict__ B0, const float* __restrict__ B1, const float* __restrict__ B2,
    int ldB, int headed, int kt_cnt,
    const float* __restrict__ bi0, const float* __restrict__ bi1, const float* __restrict__ bi2,
    float* __restrict__ o0, float* __restrict__ o1, float* __restrict__ o2, float* __restrict__ o3,
    half_t* __restrict__ oh, int Nout, int mode)
{
    constexpr int SB_B   = NTT * 2 + 16;
    constexpr int BTILE  = 32 * SB_B;
    constexpr int NWARP_N = NTT / 64;
    constexpr int NCHUNK = NTT / 64;

    extern __shared__ char smem[];
    const uint32_t sbase = smem_u32(smem);
    const int tid  = threadIdx.x;
    const int lane = tid & 31, wid = tid >> 5;
    const int wm = wid & 1, wn = wid >> 1;

    const int row0 = blockIdx.y * 128;
    const int col0 = blockIdx.x * NTT;
    const int kt_off = blockIdx.z * kt_cnt;
    const int nt = kt_cnt;

    const float* Whead = nullptr;
    int colh = 0;
    if (headed) {
        const int mat = col0 >> 11;
        Whead = (mat == 0) ? B0 : (mat == 1) ? B1 : B2;
        colh = col0 & 2047;
    }

    const uint32_t a_off = (uint32_t)((wm * 64 + (lane & 7) + ((lane >> 3) & 1) * 8) * SA_B
                                      + ((lane >> 4) & 1) * 16);
    const uint32_t b_off = (uint32_t)(((lane & 7) + ((lane >> 3) & 1) * 8) * SB_B
                                      + wn * (NTT / 2) + ((lane >> 4) & 1) * 16);

    float4 breg[2 * NCHUNK];
    auto ldg_b = [&](int t) {
        const int kk = (kt_off + t) * 32;
#pragma unroll
        for (int i = 0; i < NCHUNK; i++) {
            int idx = tid + i * 256;
            int r = idx / (NTT / 8), c8 = idx % (NTT / 8);
            const float* p;
            if (headed) {
                int cg = colh + c8 * 8;
                p = Whead + ((size_t)(cg >> 7) * D + kk + r) * DH + (cg & 127);
            } else {
                p = B0 + (size_t)(kk + r) * ldB + col0 + c8 * 8;
            }
            breg[2 * i]     = *(const float4*)p;
            breg[2 * i + 1] = *(const float4*)(p + 4);
        }
    };
    auto sts_b = [&](int slot) {
        char* sB = smem + NSTAGE * ATILE + slot * BTILE;
#pragma unroll
        for (int i = 0; i < NCHUNK; i++) {
            int idx = tid + i * 256;
            int r = idx / (NTT / 8), c8 = idx % (NTT / 8);
            uint4 w;
            ((__half2*)&w)[0] = __floats2half2_rn(breg[2*i].x,   breg[2*i].y);
            ((__half2*)&w)[1] = __floats2half2_rn(breg[2*i].z,   breg[2*i].w);
            ((__half2*)&w)[2] = __floats2half2_rn(breg[2*i+1].x, breg[2*i+1].y);
            ((__half2*)&w)[3] = __floats2half2_rn(breg[2*i+1].z, breg[2*i+1].w);
            *(uint4*)(sB + r * SB_B + c8 * 16) = w;
        }
    };
    auto load_a = [&](int t, int slot) {
        const int kk = (kt_off + t) * 32;
        const half_t* Ab = A + (size_t)row0 * ldA + kk;
        const uint32_t sA = sbase + slot * ATILE;
#pragma unroll
        for (int i = 0; i < 2; i++) {
            int id = tid + i * 256;
            int r = id >> 2, c = id & 3;
            cp16(sA + (uint32_t)(r * SA_B + c * 16), Ab + (size_t)r * ldA + c * 8);
        }
        cp_commit();
    };

    float acc[4][2 * NWARP_N][4];
#pragma unroll
    for (int i = 0; i < 4; i++)
#pragma unroll
        for (int j = 0; j < 2 * NWARP_N; j++)
#pragma unroll
            for (int p = 0; p < 4; p++) acc[i][j][p] = 0.f;

    ldg_b(0);
    load_a(0, 0);
    if (nt > 1) load_a(1, 1);

    for (int t = 0; t < nt; t++) {
        sts_b(t & 1);
        if (t + 1 < nt) ldg_b(t + 1);
        if (t + 2 < nt) load_a(t + 2, (t + 2) % NSTAGE);
        {
            int rem = nt - 1 - t;
            if (rem >= 2) cp_wait<2>();
            else if (rem == 1) cp_wait<1>();
            else cp_wait<0>();
        }
        __syncthreads();

        const uint32_t sA = sbase + (t % NSTAGE) * ATILE;
        const uint32_t sB = sbase + NSTAGE * ATILE + (uint32_t)((t & 1) * BTILE);
#pragma unroll
        for (int ks = 0; ks < 2; ks++) {
            uint32_t bfr[NWARP_N][4];
#pragma unroll
            for (int np = 0; np < NWARP_N; np++)
                ldsm4t(bfr[np], sB + b_off + (uint32_t)(ks * 16 * SB_B + np * 32));
            uint32_t afr[4][4];
#pragma unroll
            for (int mt = 0; mt < 4; mt++)
                ldsm4(afr[mt], sA + a_off + (uint32_t)(mt * 16 * SA_B + ks * 32));
#pragma unroll
            for (int mt = 0; mt < 4; mt++)
#pragma unroll
                for (int nc = 0; nc < 2 * NWARP_N; nc++)
                    mma16816(acc[mt][nc], afr[mt], &bfr[nc >> 1][(nc & 1) * 2]);
        }
    }

    // ---- epilogue -----------------------------------------------------------
    const int rbase  = row0 + wm * 64 + (lane >> 2);
    const int cgbase = col0 + wn * (NTT / 4) + (lane & 3) * 2;

    if (mode == 0) {
        const int mat = col0 >> 11;
        float* outp = (mat == 0) ? o0 : (mat == 1) ? o1 : o2;
        const float* bp = (mat == 0) ? bi0 : (mat == 1) ? bi1 : bi2;
        const int clb = cgbase & 2047;
#pragma unroll
        for (int mt = 0; mt < 4; mt++) {
            int r = rbase + mt * 16;
#pragma unroll
            for (int nc = 0; nc < 2 * NWARP_N; nc++) {
                int cc = clb + nc * 8;
                *(float2*)(outp + (size_t)r * 2048 + cc) =
                    make_float2(acc[mt][nc][0] + bp[cc], acc[mt][nc][1] + bp[cc + 1]);
                *(float2*)(outp + (size_t)(r + 8) * 2048 + cc) =
                    make_float2(acc[mt][nc][2] + bp[cc], acc[mt][nc][3] + bp[cc + 1]);
            }
        }
    } else if (mode == 2) {
#pragma unroll
        for (int mt = 0; mt < 4; mt++) {
            int r = rbase + mt * 16;
#pragma unroll
            for (int nc = 0; nc < 2 * NWARP_N; nc++) {
                int cc = cgbase + nc * 8;
                float v0 = fmaxf(acc[mt][nc][0] + bi0[cc], 0.f);
                float v1 = fmaxf(acc[mt][nc][1] + bi0[cc + 1], 0.f);
                float v2 = fmaxf(acc[mt][nc][2] + bi0[cc], 0.f);
                float v3 = fmaxf(acc[mt][nc][3] + bi0[cc + 1], 0.f);
                *(__half2*)(oh + (size_t)r * Nout + cc) = __floats2half2_rn(v0, v1);
                *(__half2*)(oh + (size_t)(r + 8) * Nout + cc) = __floats2half2_rn(v2, v3);
            }
        }
    } else {  // mode 3
        float* outp = (blockIdx.z == 0) ? o0 : (blockIdx.z == 1) ? o1
                    : (blockIdx.z == 2) ? o2 : o3;
#pragma unroll
        for (int mt = 0; mt < 4; mt++) {
            int r = rbase + mt * 16;
#pragma unroll
            for (int nc = 0; nc < 2 * NWARP_N; nc++) {
                int cc = cgbase + nc * 8;
                *(float2*)(outp + (size_t)r * Nout + cc) =
                    make_float2(acc[mt][nc][0], acc[mt][nc][1]);
                *(float2*)(outp + (size_t)(r + 8) * Nout + cc) =
                    make_float2(acc[mt][nc][2], acc[mt][nc][3]);
            }
        }
    }
}

// ---------------- combine 4 partials + bias + residual, then LN --------------
__global__ void combine_ln_kernel(const float* __restrict__ x,
                                  const float* __restrict__ P0, const float* __restrict__ P1,
                                  const float* __restrict__ P2, const float* __restrict__ P3,
                                  const float* __restrict__ bias,
                                  const float* __restrict__ g, const float* __restrict__ b,
                                  float* __restrict__ x1, half_t* __restrict__ oh) {
    __shared__ float red[8];
    const int row = blockIdx.x;
    const int tid = threadIdx.x;
    const size_t rb = (size_t)row * D;

    float vals[8];
    float s = 0.f;
#pragma unroll
    for (int i = 0; i < 8; i++) {
        int c = tid + i * 256;
        float v = x[rb + c] + P0[rb + c] + P1[rb + c] + P2[rb + c] + P3[rb + c] + bias[c];
        x1[rb + c] = v;
        vals[i] = v;
        s += v;
    }
#pragma unroll
    for (int off = 16; off; off >>= 1) s += __shfl_xor_sync(0xffffffffu, s, off);
    if ((tid & 31) == 0) red[tid >> 5] = s;
    __syncthreads();
    s = 0.f;
#pragma unroll
    for (int i = 0; i < 8; i++) s += red[i];
    const float m = s * (1.f / D);
    __syncthreads();

    float s2 = 0.f;
#pragma unroll
    for (int i = 0; i < 8; i++) { float d = vals[i] - m; s2 += d * d; }
#pragma unroll
    for (int off = 16; off; off >>= 1) s2 += __shfl_xor_sync(0xffffffffu, s2, off);
    if ((tid & 31) == 0) red[tid >> 5] = s2;
    __syncthreads();
    s2 = 0.f;
#pragma unroll
    for (int i = 0; i < 8; i++) s2 += red[i];
    const float rstd = rsqrtf(s2 * (1.f / D) + 1e-5f);

#pragma unroll
    for (int i = 0; i < 8; i++) {
        int c = tid + i * 256;
        oh[rb + c] = __float2half_rn((vals[i] - m) * rstd * g[c] + b[c]);
    }
}

// ---------------- final combine: out = x1 + P0..P3 + b2 ----------------------
__global__ void combine_kernel(const float* __restrict__ x1,
                               const float* __restrict__ P0, const float* __restrict__ P1,
                               const float* __restrict__ P2, const float* __restrict__ P3,
                               const float* __restrict__ b2, float* __restrict__ out) {
    size_t i = (size_t)(blockIdx.x * blockDim.x + threadIdx.x) * 4;
    int col = (int)(i & (D - 1));
    float4 a = *(const float4*)(x1 + i);
    float4 p = *(const float4*)(P0 + i);
    float4 q = *(const float4*)(P1 + i);
    float4 r = *(const float4*)(P2 + i);
    float4 s = *(const float4*)(P3 + i);
    float4 b = *(const float4*)(b2 + col);
    float4 w;
    w.x = a.x + p.x + q.x + r.x + s.x + b.x;
    w.y = a.y + p.y + q.y + r.y + s.y + b.y;
    w.z = a.z + p.z + q.z + r.z + s.z + b.z;
    w.w = a.w + p.w + q.w + r.w + s.w + b.w;
    *(float4*)(out + i) = w;
}

// ---------------- host orchestration -----------------------------------------
extern "C" void kernel_launch(void* const* d_in, const int* in_sizes, int n_in,
                              void* d_out, int out_size) {
    const float* x   = (const float*)d_in[0];
    const float* Wq  = (const float*)d_in[1];
    const float* bq  = (const float*)d_in[2];
    const float* Wk  = (const float*)d_in[3];
    const float* bk  = (const float*)d_in[4];
    const float* Wv  = (const float*)d_in[5];
    const float* bv  = (const float*)d_in[6];
    const float* Wo  = (const float*)d_in[7];
    const float* bo  = (const float*)d_in[8];
    const float* W1  = (const float*)d_in[9];
    const float* b1  = (const float*)d_in[10];
    const float* W2  = (const float*)d_in[11];
    const float* b2  = (const float*)d_in[12];
    const float* g1  = (const float*)d_in[13];
    const float* be1 = (const float*)d_in[14];
    const float* g2  = (const float*)d_in[15];
    const float* be2 = (const float*)d_in[16];
    float* out = (float*)d_out;

    half_t *ph, *po, *ph2, *pf1;
    float *pq, *pk, *pv, *px1, *pP0, *pP1, *pP2, *pP3;
    cudaGetSymbolAddress((void**)&ph,  g_h);
    cudaGetSymbolAddress((void**)&pq,  g_q);
    cudaGetSymbolAddress((void**)&pk,  g_k);
    cudaGetSymbolAddress((void**)&pv,  g_v);
    cudaGetSymbolAddress((void**)&po,  g_o);
    cudaGetSymbolAddress((void**)&px1, g_x1);
    cudaGetSymbolAddress((void**)&ph2, g_h2);
    cudaGetSymbolAddress((void**)&pf1, g_f1);
    cudaGetSymbolAddress((void**)&pP0, g_P0);
    cudaGetSymbolAddress((void**)&pP1, g_P1);
    cudaGetSymbolAddress((void**)&pP2, g_P2);
    cudaGetSymbolAddress((void**)&pP3, g_P3);

    const int GSM128 = NSTAGE * ATILE + 2 * (32 * (128 * 2 + 16));   // 58368
    const int GSM256 = NSTAGE * ATILE + 2 * (32 * (256 * 2 + 16));   // 74752
    static bool attr_done = false;
    if (!attr_done) {
        cudaFuncSetAttribute(gemm_kernel<128>, cudaFuncAttributeMaxDynamicSharedMemorySize, GSM128);
        cudaFuncSetAttribute(gemm_kernel<256>, cudaFuncAttributeMaxDynamicSharedMemorySize, GSM256);
        attr_done = true;
    }

    // ---- h = LN(x) ----
    ln_kernel<<<Bsz, 256>>>(x, g1, be1, ph);

    // ---- q|k|v = h @ [Wq|Wk|Wv] + b (headed, NT=256): 96 CTAs, kt=64 ----
    gemm_kernel<256><<<dim3(3 * D / 256, Bsz / 128, 1), 256, GSM256>>>(
        ph, D, Wq, Wk, Wv, 0, 1, D / 32,
        bq, bk, bv, pq, pk, pv, nullptr, nullptr, 2048, 0);

    // ---- attention (warp-only) ----
    attn_kernel<<<Bsz * Hh, 32>>>(pq, pk, pv, po);

    // ---- P_z = o @ Wo (NT=256, K-split x4): 128 CTAs, kt=16 ----
    gemm_kernel<256><<<dim3(D / 256, Bsz / 128, 4), 256, GSM256>>>(
        po, D, Wo, nullptr, nullptr, D, 0, (D / 4) / 32,
        nullptr, nullptr, nullptr, pP0, pP1, pP2, pP3, nullptr, D, 3);

    // ---- x1 = x + sum(P) + bo; h2 = LN(x1) (fused) ----
    combine_ln_kernel<<<Bsz, 256>>>(x, pP0, pP1, pP2, pP3, bo, g2, be2, px1, ph2);

    // ---- f1 = relu(h2 @ W1 + b1) -> fp16 (NT=256): 128 CTAs, kt=64 ----
    gemm_kernel<256><<<dim3(FF / 256, Bsz / 128, 1), 256, GSM256>>>(
        ph2, D, W1, nullptr, nullptr, FF, 0, D / 32,
        b1, nullptr, nullptr, nullptr, nullptr, nullptr, nullptr, pf1, FF, 2);

    // ---- P_z = f1 @ W2 (NT=256, K-split x4): 128 CTAs, kt=64 ----
    gemm_kernel<256><<<dim3(D / 256, Bsz / 128, 4), 256, GSM256>>>(
        pf1, FF, W2, nullptr, nullptr, D, 0, (FF / 4) / 32,
        nullptr, nullptr, nullptr, pP0, pP1, pP2, pP3, nullptr, D, 3);

    // ---- out = x1 + sum(P) + b2 ----
    combine_kernel<<<(Bsz * D / 4) / 512, 512>>>(px1, pP0, pP1, pP2, pP3, b2, out);
}